// round 4
// baseline (speedup 1.0000x reference)
#include <cuda_runtime.h>
#include <cstdint>

#define NC       32
#define NSTEPS   32
#define DDIM     30
#define BLOCK    256
#define PPT      8
#define MBINS    16384            // level-1 bins per theta (2^14)
#define SUBDIV   16               // level-2 refinement
#define FBINS    (MBINS * SUBDIV) // 2^18 fine bins
#define BPB      256              // bins per setup block
#define NT_MAX   8
#define MAXSLOTS 4096
#define SEQW     6                // 6 words x 6 steps x 5 bits >= 32 steps

// Level-1: per-(theta,bin) composed affine; x==NaN => impure, y = slot (int) or -1.
__device__ float2 g_binAB[NT_MAX * MBINS];
// Level-2: per-slot 16 sub-bin affines; x==NaN => truly impure (iterate).
__device__ float2 g_sub[NT_MAX * MAXSLOTS * SUBDIV];
__device__ int    g_slot2bin[NT_MAX * MAXSLOTS];
__device__ int    g_cnt[NT_MAX];

__device__ __forceinline__ void build_table(const float* __restrict__ theta,
                                            const float* __restrict__ basis,
                                            int t, int tid,
                                            float* s0, float* s1)
{
    if (tid < NC) {
        const float dT = 1.0f / (float)NSTEPS;
        const float* __restrict__ ba = basis + (2 * tid)     * DDIM;
        const float* __restrict__ bb = basis + (2 * tid + 1) * DDIM;
        const float* __restrict__ th = theta + t * DDIM;
        float a = 0.0f, b = 0.0f;
        #pragma unroll
        for (int j = 0; j < DDIM; ++j) {
            float tj = th[j];
            a = fmaf(ba[j], tj, a);
            b = fmaf(bb[j], tj, b);
        }
        a *= dT;
        b *= dT;
        float ea  = expf(a);
        float phi = (fabsf(a) < 1e-6f) ? (1.0f + 0.5f * a) : (expm1f(a) / a);
        s0[tid] = ea;
        s1[tid] = b * phi;
    }
}

__device__ __forceinline__ int step_cell(float x)
{
    float xc = fminf(fmaxf(x * (float)NC, 0.0f), (float)(NC - 1));
    return (int)xc;
}

__global__ void zero_kernel()
{
    if (threadIdx.x < NT_MAX) g_cnt[threadIdx.x] = 0;
}

// ---------------------------------------------------------------------------
// Pass A: classify level-1 bins; pure -> (A,B); impure -> allocate slot.
// ---------------------------------------------------------------------------
__global__ __launch_bounds__(BLOCK)
void setup_kernel(const float* __restrict__ theta,
                  const float* __restrict__ basis)
{
    __shared__ float    s0[NC], s1[NC];
    __shared__ float    sA[BPB + 1], sB[BPB + 1];
    __shared__ uint32_t sSeq[BPB + 1][SEQW];

    const int t   = blockIdx.y;
    const int bx  = blockIdx.x;
    const int tid = threadIdx.x;

    build_table(theta, basis, t, tid, s0, s1);
    __syncthreads();

    for (int j = tid; j <= BPB; j += BLOCK) {
        float x = (float)(bx * BPB + j) * (1.0f / (float)MBINS); // exact fp32
        float A = 1.0f, B = 0.0f;
        uint32_t sw[SEQW];
        #pragma unroll
        for (int w = 0; w < SEQW; ++w) sw[w] = 0u;
        #pragma unroll
        for (int s = 0; s < NSTEPS; ++s) {
            int c = step_cell(x);
            sw[s / 6] = (sw[s / 6] << 5) | (uint32_t)c;
            float t0 = s0[c], t1 = s1[c];
            x = fmaf(t0, x, t1);
            A = A * t0;
            B = fmaf(t0, B, t1);
        }
        sA[j] = A;
        sB[j] = B;
        #pragma unroll
        for (int w = 0; w < SEQW; ++w) sSeq[j][w] = sw[w];
    }
    __syncthreads();

    if (tid < BPB) {
        bool pure = true;
        #pragma unroll
        for (int w = 0; w < SEQW; ++w)
            pure = pure && (sSeq[tid][w] == sSeq[tid + 1][w]);
        int bin = bx * BPB + tid;
        float2 r;
        if (pure) {
            r = make_float2(sA[tid], sB[tid]);
        } else {
            int slot = atomicAdd(&g_cnt[t], 1);
            if (slot < MAXSLOTS) {
                g_slot2bin[t * MAXSLOTS + slot] = bin;
                r = make_float2(__int_as_float(0x7FC00000), __int_as_float(slot));
            } else {
                r = make_float2(__int_as_float(0x7FC00000), __int_as_float(-1));
            }
        }
        g_binAB[t * MBINS + bin] = r;
    }
}

// ---------------------------------------------------------------------------
// Pass B: refine impure bins into 16 sub-bins each.
// ---------------------------------------------------------------------------
__global__ __launch_bounds__(BLOCK)
void refine_kernel(const float* __restrict__ theta,
                   const float* __restrict__ basis)
{
    __shared__ float s0[NC], s1[NC];
    const int t   = blockIdx.y;
    const int tid = threadIdx.x;

    build_table(theta, basis, t, tid, s0, s1);
    __syncthreads();

    const int nslots = min(g_cnt[t], MAXSLOTS);
    const int nwork  = nslots * SUBDIV;

    for (int i = blockIdx.x * BLOCK + tid; i < nwork; i += gridDim.x * BLOCK) {
        int slot = i >> 4;
        int sub  = i & (SUBDIV - 1);
        int bin  = g_slot2bin[t * MAXSLOTS + slot];
        int fb   = bin * SUBDIV + sub;

        float xl = (float)fb       * (1.0f / (float)FBINS);  // exact fp32
        float xr = (float)(fb + 1) * (1.0f / (float)FBINS);
        float A = 1.0f, B = 0.0f;
        bool pure = true;
        #pragma unroll
        for (int s = 0; s < NSTEPS; ++s) {
            int cl = step_cell(xl);
            int cr = step_cell(xr);
            pure = pure && (cl == cr);
            float t0 = s0[cl], t1 = s1[cl];
            xl = fmaf(t0, xl, t1);
            A  = A * t0;
            B  = fmaf(t0, B, t1);
            xr = fmaf(s0[cr], xr, s1[cr]);
        }
        g_sub[(t * MAXSLOTS + slot) * SUBDIV + sub] =
            pure ? make_float2(A, B)
                 : make_float2(__int_as_float(0x7FC00000), 0.0f);
    }
}

// ---------------------------------------------------------------------------
// Main: phase-batched lookups, two-level fallback, tiny compacted slow path.
// ---------------------------------------------------------------------------
__global__ __launch_bounds__(BLOCK)
void main_kernel(const float* __restrict__ points,
                 const float* __restrict__ theta,
                 const float* __restrict__ basis,
                 float* __restrict__ out,
                 int n_points)
{
    __shared__ float s0[NC], s1[NC];
    __shared__ int   s_list[BLOCK * PPT];
    __shared__ int   s_cnt;

    const int t    = blockIdx.y;
    const int tid  = threadIdx.x;
    const int lane = tid & 31;

    if (tid == 0) s_cnt = 0;
    build_table(theta, basis, t, tid, s0, s1);
    __syncthreads();

    const float2* __restrict__ bt  = g_binAB + t * MBINS;
    const float2* __restrict__ sb  = g_sub + (size_t)t * MAXSLOTS * SUBDIV;
    const int base = blockIdx.x * (BLOCK * PPT) + tid;
    float* __restrict__ o = out + (size_t)t * (size_t)n_points;

    // Phase 1: all point loads (independent)
    float x[PPT];
    #pragma unroll
    for (int k = 0; k < PPT; ++k) {
        int idx = base + k * BLOCK;
        x[k] = (idx < n_points) ? points[idx] : 0.0f;
    }

    // Phase 2: all fine-bin indices (exact floor) + all level-1 gathers
    int u[PPT];
    #pragma unroll
    for (int k = 0; k < PPT; ++k) {
        int v = (int)__fmul_rz(x[k], (float)FBINS);
        u[k] = min(max(v, 0), FBINS - 1);
    }
    float2 ab[PPT];
    #pragma unroll
    for (int k = 0; k < PPT; ++k)
        ab[k] = __ldg(&bt[u[k] >> 4]);

    // Phase 3: consume; rare level-2 gather; rarer slow-flag
    #pragma unroll
    for (int k = 0; k < PPT; ++k) {
        int  idx   = base + k * BLOCK;
        bool valid = (idx < n_points);
        float2 a = ab[k];
        bool done = false;
        float r = 0.0f;
        if (a.x == a.x) {                         // level-1 pure
            r = fmaf(a.x, x[k], a.y);
            done = true;
        } else {
            int slot = __float_as_int(a.y);
            if (slot >= 0) {
                float2 a2 = __ldg(&sb[slot * SUBDIV + (u[k] & (SUBDIV - 1))]);
                if (a2.x == a2.x) {               // level-2 pure
                    r = fmaf(a2.x, x[k], a2.y);
                    done = true;
                }
            }
        }
        if (valid && done) o[idx] = r;

        bool slow = valid && !done;
        unsigned m = __ballot_sync(0xFFFFFFFFu, slow);
        if (m) {
            int leader = __ffs(m) - 1;
            int wbase  = 0;
            if (lane == leader) wbase = atomicAdd(&s_cnt, __popc(m));
            wbase = __shfl_sync(0xFFFFFFFFu, wbase, leader);
            if (slow)
                s_list[wbase + __popc(m & ((1u << lane) - 1u))] = idx;
        }
    }
    __syncthreads();

    // Slow path: ~0.4% of points, exact reference iteration, packed warps.
    const int n_imp = s_cnt;
    for (int e = tid; e < n_imp; e += BLOCK) {
        int idx = s_list[e];
        float xx = points[idx];
        #pragma unroll
        for (int s = 0; s < NSTEPS; ++s) {
            int c = step_cell(xx);
            xx = fmaf(s0[c], xx, s1[c]);
        }
        o[idx] = xx;
    }
}

extern "C" void kernel_launch(void* const* d_in, const int* in_sizes, int n_in,
                              void* d_out, int out_size)
{
    const float* points = (const float*)d_in[0];  // [1, n_points]
    const float* theta  = (const float*)d_in[1];  // [n_theta, 30]
    const float* basis  = (const float*)d_in[2];  // [64, 30]
    float* out = (float*)d_out;                   // [n_theta, 1, n_points]

    const int n_points = in_sizes[0];
    const int n_theta  = in_sizes[1] / DDIM;

    zero_kernel<<<1, 32>>>();

    dim3 agrid(MBINS / BPB, n_theta);
    setup_kernel<<<agrid, BLOCK>>>(theta, basis);

    dim3 bgrid(64, n_theta);
    refine_kernel<<<bgrid, BLOCK>>>(theta, basis);

    dim3 mgrid((n_points + BLOCK * PPT - 1) / (BLOCK * PPT), n_theta);
    main_kernel<<<mgrid, BLOCK>>>(points, theta, basis, out, n_points);
}